// round 12
// baseline (speedup 1.0000x reference)
#include <cuda_runtime.h>
#include <cuda_bf16.h>
#include <math_constants.h>

#define BATCH 2048
#define TLEN  4096
#define NSIG  7
#define PRED  64

typedef unsigned long long ull;

__constant__ float c_lrs[NSIG] = {0.01f, 0.08f, 0.1f, 0.15f, 0.2f, 0.25f, 1.0f};

// Scratch (static __device__ — no allocations allowed)
__device__ float g_errs[BATCH * NSIG];
__device__ float g_levels[BATCH * NSIG];
__device__ int   g_bestRow[BATCH];
__device__ int   g_sigIdx[BATCH];
__device__ float g_filt[(size_t)BATCH * TLEN];   // only ~log2(B) rows ever written
__device__ unsigned g_scanDone = 0;              // last-block counter (self-resets)

// ---- packed f32x2 helpers (Blackwell; PTX-only path) -----------------------
__device__ __forceinline__ ull pack2(float lo, float hi) {
    ull r; asm("mov.b64 %0, {%1, %2};" : "=l"(r) : "f"(lo), "f"(hi)); return r;
}
__device__ __forceinline__ void unpack2(ull v, float& lo, float& hi) {
    asm("mov.b64 {%0, %1}, %2;" : "=f"(lo), "=f"(hi) : "l"(v));
}
__device__ __forceinline__ ull ffma2(ull a, ull b, ull c) {
    ull d; asm("fma.rn.f32x2 %0, %1, %2, %3;" : "=l"(d) : "l"(a), "l"(b), "l"(c)); return d;
}
__device__ __forceinline__ ull fmul2(ull a, ull b) {
    ull d; asm("mul.rn.f32x2 %0, %1, %2;" : "=l"(d) : "l"(a), "l"(b)); return d;
}

// ---------------------------------------------------------------------------
// K1: innovation-form scan + last-block pick.
// SHAPE: 128 threads/block, 32 elems/thread — the measured-fastest scan
// config (19.6us) across all tried shapes (64x64, 128x32, 256x16).
// CONST-A scan: chunk transfer A = a^32 is input-independent, so every
// Hillis-Steele multiplier is the constant a^(32*off) -> C-only shuffles;
// Aex = a^(32*lane) via interleaved conditional squarings.
// d_t = a*d_{t-1} + dy_t, d_0 = 0; err = sum d^2; level = y_last - a*d_last.
// ---------------------------------------------------------------------------
__global__ void __launch_bounds__(128) scan_pick_kernel(const float* __restrict__ data) {
    constexpr int TPB = 128;
    constexpr int NW  = TPB / 32;          // 4 warps
    __shared__ float sLast[TPB];
    __shared__ ull   sWC[NW * 3];
    __shared__ float sE[NSIG][TPB];
    __shared__ float sMin[BATCH];          // pick (last block only)
    __shared__ int   sIdx[BATCH];
    __shared__ int   sIsLast;

    int r = blockIdx.x;
    int t = threadIdx.x;
    int lane = t & 31;
    int w = t >> 5;

    const float4* row = (const float4*)(data + (size_t)r * TLEN);
    float4 v[8];                           // 32 floats, time-contiguous
#pragma unroll
    for (int i = 0; i < 8; i++) v[i] = __ldg(&row[t * 8 + i]);

    sLast[t] = v[7].w;
    __syncthreads();
    float yprev = t ? sLast[t - 1] : v[0].x;   // dy_0 = 0 for t==0
    float ylast = v[7].w;

    ull A1[3];
    A1[0] = pack2(0.99f, 0.92f);
    A1[1] = pack2(0.90f, 0.85f);
    A1[2] = pack2(0.80f, 0.75f);

    // --- phase1: Horner of dy per pair; dy stored back into v ---------------
    ull H[3] = {0ull, 0ull, 0ull};
    float yp = yprev;
#pragma unroll
    for (int i = 0; i < 8; i++) {
#define P1STEP(REF) { float yy = (REF); float dl = yy - yp; yp = yy; (REF) = dl; \
        ull d2 = pack2(dl, dl);                       \
        H[0] = ffma2(A1[0], H[0], d2);                \
        H[1] = ffma2(A1[1], H[1], d2);                \
        H[2] = ffma2(A1[2], H[2], d2); }
        P1STEP(v[i].x) P1STEP(v[i].y) P1STEP(v[i].z) P1STEP(v[i].w)
#undef P1STEP
    }

    // Ak = a^32 (5 packed squarings); C = chunk transfer constant term
    ull Ak[3], C[3], Aex[3];
    ull ONE2 = pack2(1.0f, 1.0f);
#pragma unroll
    for (int p = 0; p < 3; p++) {
        ull a = A1[p];
        a = fmul2(a, a); a = fmul2(a, a); a = fmul2(a, a);
        a = fmul2(a, a); a = fmul2(a, a);
        Ak[p] = a;                         // a^32
        C[p]  = H[p];                      // no sigma multiply in d-form
        Aex[p] = ONE2;
    }

    // --- constant-A warp scan: only C is shuffled ----------------------------
#pragma unroll
    for (int off = 1; off < 32; off <<= 1) {
#pragma unroll
        for (int p = 0; p < 3; p++) {
            ull pc = __shfl_up_sync(0xffffffffu, C[p], off);
            if (lane >= off) C[p] = ffma2(Ak[p], pc, C[p]);   // Ak = a^(32*off)
            if (lane & off)  Aex[p] = fmul2(Aex[p], Ak[p]);   // -> a^(32*lane)
            Ak[p] = fmul2(Ak[p], Ak[p]);
        }
    }
    // now Ak = a^1024 (per-warp total transfer coefficient, constant)
    if (lane == 31) {
#pragma unroll
        for (int p = 0; p < 3; p++) sWC[w * 3 + p] = C[p];
    }
    __syncthreads();

    // entry d: cross-warp fold (d_init = 0, constant a^1024) + in-warp exclusive
    ull Dent[3];
#pragma unroll
    for (int p = 0; p < 3; p++) {
        ull pc = 0ull;
#pragma unroll
        for (int j = 0; j < NW - 1; j++)
            if (j < w) pc = ffma2(Ak[p], pc, sWC[j * 3 + p]);
        ull eC = __shfl_up_sync(0xffffffffu, C[p], 1);
        Dent[p] = lane ? ffma2(Aex[p], pc, eC) : pc;
    }

    // --- phase2: d-recurrence + error accumulation --------------------------
    ull D[3] = {Dent[0], Dent[1], Dent[2]};
    ull E[3] = {0ull, 0ull, 0ull};
    float e6 = 0.0f;
#pragma unroll
    for (int i = 0; i < 8; i++) {
#define P2STEP(REF) { float dl = (REF); ull d2 = pack2(dl, dl);  \
        D[0] = ffma2(A1[0], D[0], d2); E[0] = ffma2(D[0], D[0], E[0]); \
        D[1] = ffma2(A1[1], D[1], d2); E[1] = ffma2(D[1], D[1], E[1]); \
        D[2] = ffma2(A1[2], D[2], d2); E[2] = ffma2(D[2], D[2], E[2]); \
        e6 = fmaf(dl, dl, e6); }
        P2STEP(v[i].x) P2STEP(v[i].y) P2STEP(v[i].z) P2STEP(v[i].w)
#undef P2STEP
    }

    float ev[NSIG];
    unpack2(E[0], ev[0], ev[1]);
    unpack2(E[1], ev[2], ev[3]);
    unpack2(E[2], ev[4], ev[5]);
    ev[6] = e6;
#pragma unroll
    for (int q = 0; q < NSIG; q++) sE[q][t] = ev[q];

    if (t == TPB - 1) {                    // level_final = y_last - a*d_last
        float d0, d1;
        unpack2(D[0], d0, d1);
        g_levels[r * NSIG + 0] = fmaf(-0.99f, d0, ylast);
        g_levels[r * NSIG + 1] = fmaf(-0.92f, d1, ylast);
        unpack2(D[1], d0, d1);
        g_levels[r * NSIG + 2] = fmaf(-0.90f, d0, ylast);
        g_levels[r * NSIG + 3] = fmaf(-0.85f, d1, ylast);
        unpack2(D[2], d0, d1);
        g_levels[r * NSIG + 4] = fmaf(-0.80f, d0, ylast);
        g_levels[r * NSIG + 5] = fmaf(-0.75f, d1, ylast);
        g_levels[r * NSIG + 6] = ylast;    // sigma=1
    }
    __syncthreads();

    if (t < 64) {
#pragma unroll
        for (int q = 0; q < NSIG; q++) sE[q][t] += sE[q][t + 64];
    }
    __syncthreads();
    if (t < 32) {
#pragma unroll
        for (int q = 0; q < NSIG; q++) {
            float x = sE[q][t] + sE[q][t + 32];
#pragma unroll
            for (int off = 16; off > 0; off >>= 1)
                x += __shfl_down_sync(0xffffffffu, x, off);
            if (t == 0) g_errs[r * NSIG + q] = x * (1.0f / (float)TLEN);
        }
    }

    // ===== last-block pick (threadfence reduction pattern) =====
    __threadfence();                       // publish this block's errs/levels
    __syncthreads();
    if (t == 0) {
        unsigned old = atomicAdd(&g_scanDone, 1u);
        sIsLast = (old == (unsigned)(BATCH - 1));
        if (sIsLast) {
            g_scanDone = 0;                // reset for next graph replay
            __threadfence();               // acquire all blocks' writes
        }
    }
    __syncthreads();
    if (!sIsLast) return;

    for (int b = t; b < BATCH; b += TPB) {
        const float* e = g_errs + b * NSIG;
        float best = e[0]; int bi = 0;
#pragma unroll
        for (int s = 1; s < NSIG; s++) {
            float vv = e[s];
            if (vv < best) { best = vv; bi = s; }
        }
        sMin[b] = best; sIdx[b] = bi;
    }
    __syncthreads();

    if (t < 32) {
        float carryV = CUDART_INF_F;
        int   carryR = 0;
        for (int c = 0; c < BATCH / 32; c++) {
            int b = c * 32 + lane;
            float vv = sMin[b];
            int   rr = b;
#pragma unroll
            for (int off = 1; off < 32; off <<= 1) {
                float pv = __shfl_up_sync(0xffffffffu, vv, off);
                int   pr = __shfl_up_sync(0xffffffffu, rr, off);
                if (lane >= off && !(vv < pv)) { vv = pv; rr = pr; }
            }
            if (!(vv < carryV)) { vv = carryV; rr = carryR; }
            g_bestRow[b] = rr;
            g_sigIdx[b]  = sIdx[rr];
            carryV = __shfl_sync(0xffffffffu, vv, 31);
            carryR = __shfl_sync(0xffffffffu, rr, 31);
        }
    }
}

// ---------------------------------------------------------------------------
// K2: recompute & store the filtered series only for rows that are ever
// "best" (bestRow[r] == r); chunked scan, 128 threads. filt is PRIOR level.
// (level-form, proven output rounding; only ~log2(B) blocks do work)
// ---------------------------------------------------------------------------
__global__ void __launch_bounds__(128) filt_kernel(const float* __restrict__ data) {
    constexpr int TPB = 128;
    constexpr int EPT = TLEN / TPB;       // 32 elements per thread
    __shared__ float sA[TPB], sC[TPB];
    __shared__ float s_y0;

    int r = blockIdx.x;
    if (g_bestRow[r] != r) return;        // uniform across block
    int t = threadIdx.x;

    float sigma = c_lrs[g_sigIdx[r]];
    float a = 1.0f - sigma;

    const float4* row = (const float4*)(data + (size_t)r * TLEN);
    float4 v[EPT / 4];
#pragma unroll
    for (int i = 0; i < EPT / 4; i++) v[i] = __ldg(&row[t * (EPT / 4) + i]);

    if (t == 0) s_y0 = v[0].x;
    __syncthreads();
    float y0 = s_y0;

    float H = 0.0f;
#pragma unroll
    for (int i = 0; i < EPT / 4; i++) {
        H = fmaf(a, H, v[i].x); H = fmaf(a, H, v[i].y);
        H = fmaf(a, H, v[i].z); H = fmaf(a, H, v[i].w);
    }
    float A = a;                           // a^32 via 5 squarings
    A *= A; A *= A; A *= A; A *= A; A *= A;
    float C = sigma * H;

    sA[t] = A; sC[t] = C;
    __syncthreads();
#pragma unroll
    for (int off = 1; off < TPB; off <<= 1) {
        float pa = 1.0f, pc = 0.0f;
        if (t >= off) { pa = sA[t - off]; pc = sC[t - off]; }
        __syncthreads();
        if (t >= off) { sC[t] = fmaf(sA[t], pc, sC[t]); sA[t] *= pa; }
        __syncthreads();
    }
    float L = (t == 0) ? y0 : fmaf(sA[t - 1], y0, sC[t - 1]);

    float4* out = (float4*)(g_filt + (size_t)r * TLEN) + t * (EPT / 4);
#pragma unroll
    for (int i = 0; i < EPT / 4; i++) {
        float4 y = v[i];
        float4 f;
        f.x = L; L = fmaf(sigma, y.x - L, L);
        f.y = L; L = fmaf(sigma, y.y - L, L);
        f.z = L; L = fmaf(sigma, y.z - L, L);
        f.w = L; L = fmaf(sigma, y.w - L, L);
        out[i] = f;
    }
}

// ---------------------------------------------------------------------------
// K3: out[b][t] = data[b][t] - filt[bestRow[b]][t]; first 32K threads also
// write the broadcast preds block. Pure streaming, max MLP (proven 12.0us).
// ---------------------------------------------------------------------------
__global__ void __launch_bounds__(256) diff_kernel(const float* __restrict__ data,
                                                   float* __restrict__ out) {
    const int rowq = TLEN / 4;
    int i = blockIdx.x * blockDim.x + threadIdx.x;
    if (i < BATCH * rowq) {
        int b = i / rowq;
        int c = i - b * rowq;
        int r = g_bestRow[b];
        float4 d = __ldcs((const float4*)data + i);
        float4 f = __ldg((const float4*)g_filt + (size_t)r * rowq + c);
        float4 o;
        o.x = d.x - f.x; o.y = d.y - f.y; o.z = d.z - f.z; o.w = d.w - f.w;
        __stcs((float4*)out + i, o);
    }
    if (i < BATCH * (PRED / 4)) {          // preds: 16 float4 per row
        int b = i >> 4;
        float val = g_levels[b * NSIG + g_sigIdx[b]];
        float4 o = make_float4(val, val, val, val);
        __stcs((float4*)out + BATCH * rowq + i, o);
    }
}

// ---------------------------------------------------------------------------
extern "C" void kernel_launch(void* const* d_in, const int* in_sizes, int n_in,
                              void* d_out, int out_size) {
    const float* data = (const float*)d_in[0];
    float* out = (float*)d_out;

    scan_pick_kernel<<<BATCH, 128>>>(data);
    filt_kernel<<<BATCH, 128>>>(data);
    {
        int nq = BATCH * (TLEN / 4);             // float4 count
        diff_kernel<<<(nq + 255) / 256, 256>>>(data, out);
    }
}

// round 13
// speedup vs baseline: 1.0804x; 1.0804x over previous
#include <cuda_runtime.h>
#include <cuda_bf16.h>
#include <math_constants.h>

#define BATCH 2048
#define TLEN  4096
#define NSIG  7
#define PRED  64

typedef unsigned long long ull;

__constant__ float c_lrs[NSIG] = {0.01f, 0.08f, 0.1f, 0.15f, 0.2f, 0.25f, 1.0f};

// Scratch (static __device__ — no allocations allowed)
__device__ float g_errs[BATCH * NSIG];
__device__ float g_levels[BATCH * NSIG];
__device__ int   g_bestRow[BATCH];
__device__ int   g_sigIdx[BATCH];
__device__ float g_filt[(size_t)BATCH * TLEN];   // only ~log2(B) rows ever written
__device__ unsigned g_scanDone = 0;              // last-block counter (self-resets)

// ---- packed f32x2 helpers (Blackwell; PTX-only path) -----------------------
__device__ __forceinline__ ull pack2(float lo, float hi) {
    ull r; asm("mov.b64 %0, {%1, %2};" : "=l"(r) : "f"(lo), "f"(hi)); return r;
}
__device__ __forceinline__ void unpack2(ull v, float& lo, float& hi) {
    asm("mov.b64 {%0, %1}, %2;" : "=f"(lo), "=f"(hi) : "l"(v));
}
__device__ __forceinline__ ull ffma2(ull a, ull b, ull c) {
    ull d; asm("fma.rn.f32x2 %0, %1, %2, %3;" : "=l"(d) : "l"(a), "l"(b), "l"(c)); return d;
}
__device__ __forceinline__ ull fmul2(ull a, ull b) {
    ull d; asm("mul.rn.f32x2 %0, %1, %2;" : "=l"(d) : "l"(a), "l"(b)); return d;
}

// ---------------------------------------------------------------------------
// K1: innovation-form const-A scan (128 threads x 32 elems) + PARALLEL
// last-block pick. NO streaming hints anywhere: the replay working set
// (data 32MB + out 32MB + filt) fits in L2 — let it stay resident.
// Pick: per-thread local min over 16 rows, 128-wide smem scan of thread
// totals, re-walk with carry  (was: 64 sequential chunks on one warp —
// an ~8-10us serialized tail, visible as scan_pick 30.4us vs scan 19.6us).
// ---------------------------------------------------------------------------
__global__ void __launch_bounds__(128) scan_pick_kernel(const float* __restrict__ data) {
    constexpr int TPB = 128;
    constexpr int NW  = TPB / 32;          // 4 warps
    constexpr int RPT = BATCH / TPB;       // 16 rows per thread in pick
    __shared__ float sLast[TPB];
    __shared__ ull   sWC[NW * 3];
    __shared__ float sE[NSIG][TPB];
    __shared__ float sMin[BATCH];          // per-row min err (pick, last block)
    __shared__ char  sIdx8[BATCH];         // per-row argmin sigma (3 bits)
    __shared__ float sPV[TPB];             // thread-total scan buffers
    __shared__ int   sPR[TPB];
    __shared__ int   sIsLast;

    int r = blockIdx.x;
    int t = threadIdx.x;
    int lane = t & 31;
    int w = t >> 5;

    const float4* row = (const float4*)(data + (size_t)r * TLEN);
    float4 v[8];                           // 32 floats, time-contiguous
#pragma unroll
    for (int i = 0; i < 8; i++) v[i] = __ldg(&row[t * 8 + i]);

    sLast[t] = v[7].w;
    __syncthreads();
    float yprev = t ? sLast[t - 1] : v[0].x;   // dy_0 = 0 for t==0
    float ylast = v[7].w;

    ull A1[3];
    A1[0] = pack2(0.99f, 0.92f);
    A1[1] = pack2(0.90f, 0.85f);
    A1[2] = pack2(0.80f, 0.75f);

    // --- phase1: Horner of dy per pair; dy stored back into v ---------------
    ull H[3] = {0ull, 0ull, 0ull};
    float yp = yprev;
#pragma unroll
    for (int i = 0; i < 8; i++) {
#define P1STEP(REF) { float yy = (REF); float dl = yy - yp; yp = yy; (REF) = dl; \
        ull d2 = pack2(dl, dl);                       \
        H[0] = ffma2(A1[0], H[0], d2);                \
        H[1] = ffma2(A1[1], H[1], d2);                \
        H[2] = ffma2(A1[2], H[2], d2); }
        P1STEP(v[i].x) P1STEP(v[i].y) P1STEP(v[i].z) P1STEP(v[i].w)
#undef P1STEP
    }

    // Ak = a^32 (5 packed squarings); C = chunk transfer constant term
    ull Ak[3], C[3], Aex[3];
    ull ONE2 = pack2(1.0f, 1.0f);
#pragma unroll
    for (int p = 0; p < 3; p++) {
        ull a = A1[p];
        a = fmul2(a, a); a = fmul2(a, a); a = fmul2(a, a);
        a = fmul2(a, a); a = fmul2(a, a);
        Ak[p] = a;                         // a^32
        C[p]  = H[p];                      // no sigma multiply in d-form
        Aex[p] = ONE2;
    }

    // --- constant-A warp scan: only C is shuffled ----------------------------
#pragma unroll
    for (int off = 1; off < 32; off <<= 1) {
#pragma unroll
        for (int p = 0; p < 3; p++) {
            ull pc = __shfl_up_sync(0xffffffffu, C[p], off);
            if (lane >= off) C[p] = ffma2(Ak[p], pc, C[p]);   // Ak = a^(32*off)
            if (lane & off)  Aex[p] = fmul2(Aex[p], Ak[p]);   // -> a^(32*lane)
            Ak[p] = fmul2(Ak[p], Ak[p]);
        }
    }
    // now Ak = a^1024 (per-warp total transfer coefficient, constant)
    if (lane == 31) {
#pragma unroll
        for (int p = 0; p < 3; p++) sWC[w * 3 + p] = C[p];
    }
    __syncthreads();

    // entry d: cross-warp fold (d_init = 0, constant a^1024) + in-warp exclusive
    ull Dent[3];
#pragma unroll
    for (int p = 0; p < 3; p++) {
        ull pc = 0ull;
#pragma unroll
        for (int j = 0; j < NW - 1; j++)
            if (j < w) pc = ffma2(Ak[p], pc, sWC[j * 3 + p]);
        ull eC = __shfl_up_sync(0xffffffffu, C[p], 1);
        Dent[p] = lane ? ffma2(Aex[p], pc, eC) : pc;
    }

    // --- phase2: d-recurrence + error accumulation --------------------------
    ull D[3] = {Dent[0], Dent[1], Dent[2]};
    ull E[3] = {0ull, 0ull, 0ull};
    float e6 = 0.0f;
#pragma unroll
    for (int i = 0; i < 8; i++) {
#define P2STEP(REF) { float dl = (REF); ull d2 = pack2(dl, dl);  \
        D[0] = ffma2(A1[0], D[0], d2); E[0] = ffma2(D[0], D[0], E[0]); \
        D[1] = ffma2(A1[1], D[1], d2); E[1] = ffma2(D[1], D[1], E[1]); \
        D[2] = ffma2(A1[2], D[2], d2); E[2] = ffma2(D[2], D[2], E[2]); \
        e6 = fmaf(dl, dl, e6); }
        P2STEP(v[i].x) P2STEP(v[i].y) P2STEP(v[i].z) P2STEP(v[i].w)
#undef P2STEP
    }

    float ev[NSIG];
    unpack2(E[0], ev[0], ev[1]);
    unpack2(E[1], ev[2], ev[3]);
    unpack2(E[2], ev[4], ev[5]);
    ev[6] = e6;
#pragma unroll
    for (int q = 0; q < NSIG; q++) sE[q][t] = ev[q];

    if (t == TPB - 1) {                    // level_final = y_last - a*d_last
        float d0, d1;
        unpack2(D[0], d0, d1);
        g_levels[r * NSIG + 0] = fmaf(-0.99f, d0, ylast);
        g_levels[r * NSIG + 1] = fmaf(-0.92f, d1, ylast);
        unpack2(D[1], d0, d1);
        g_levels[r * NSIG + 2] = fmaf(-0.90f, d0, ylast);
        g_levels[r * NSIG + 3] = fmaf(-0.85f, d1, ylast);
        unpack2(D[2], d0, d1);
        g_levels[r * NSIG + 4] = fmaf(-0.80f, d0, ylast);
        g_levels[r * NSIG + 5] = fmaf(-0.75f, d1, ylast);
        g_levels[r * NSIG + 6] = ylast;    // sigma=1
    }
    __syncthreads();

    if (t < 64) {
#pragma unroll
        for (int q = 0; q < NSIG; q++) sE[q][t] += sE[q][t + 64];
    }
    __syncthreads();
    if (t < 32) {
#pragma unroll
        for (int q = 0; q < NSIG; q++) {
            float x = sE[q][t] + sE[q][t + 32];
#pragma unroll
            for (int off = 16; off > 0; off >>= 1)
                x += __shfl_down_sync(0xffffffffu, x, off);
            if (t == 0) g_errs[r * NSIG + q] = x * (1.0f / (float)TLEN);
        }
    }

    // ===== last-block PARALLEL pick (threadfence reduction pattern) =====
    __threadfence();                       // publish this block's errs/levels
    __syncthreads();
    if (t == 0) {
        unsigned old = atomicAdd(&g_scanDone, 1u);
        sIsLast = (old == (unsigned)(BATCH - 1));
        if (sIsLast) {
            g_scanDone = 0;                // reset for next graph replay
            __threadfence();               // acquire all blocks' writes
        }
    }
    __syncthreads();
    if (!sIsLast) return;

    // pass1: per-row argmin over sigmas (strict < -> first min) + thread total
    float lmin = CUDART_INF_F; int lrow = 0;
#pragma unroll 4
    for (int k = 0; k < RPT; k++) {
        int b = t * RPT + k;
        const float* e = g_errs + b * NSIG;
        float best = e[0]; int bi = 0;
#pragma unroll
        for (int s = 1; s < NSIG; s++) {
            float vv = e[s];
            if (vv < best) { best = vv; bi = s; }
        }
        sMin[b] = best; sIdx8[b] = (char)bi;
        if (best < lmin) { lmin = best; lrow = b; }   // strict < => prefer-left
    }
    sPV[t] = lmin; sPR[t] = lrow;
    __syncthreads();

    // inclusive scan of thread totals, prefer-left on ties
#pragma unroll
    for (int off = 1; off < TPB; off <<= 1) {
        float pv = 0.0f; int pr = 0; bool act = (t >= off);
        if (act) { pv = sPV[t - off]; pr = sPR[t - off]; }
        __syncthreads();
        if (act && !(sPV[t] < pv)) { sPV[t] = pv; sPR[t] = pr; }
        __syncthreads();
    }

    // pass2: re-walk own rows with entering carry (exclusive = inclusive[t-1])
    float carry = (t == 0) ? CUDART_INF_F : sPV[t - 1];
    int   carryR = (t == 0) ? 0 : sPR[t - 1];
#pragma unroll 4
    for (int k = 0; k < RPT; k++) {
        int b = t * RPT + k;
        float vv = sMin[b];
        if (vv < carry) { carry = vv; carryR = b; }
        g_bestRow[b] = carryR;
        g_sigIdx[b]  = (int)sIdx8[carryR];
    }
}

// ---------------------------------------------------------------------------
// K2: recompute & store the filtered series only for rows that are ever
// "best" (bestRow[r] == r); chunked scan, 128 threads. filt is PRIOR level.
// (level-form, proven output rounding; only ~log2(B) blocks do work)
// ---------------------------------------------------------------------------
__global__ void __launch_bounds__(128) filt_kernel(const float* __restrict__ data) {
    constexpr int TPB = 128;
    constexpr int EPT = TLEN / TPB;       // 32 elements per thread
    __shared__ float sA[TPB], sC[TPB];
    __shared__ float s_y0;

    int r = blockIdx.x;
    if (g_bestRow[r] != r) return;        // uniform across block
    int t = threadIdx.x;

    float sigma = c_lrs[g_sigIdx[r]];
    float a = 1.0f - sigma;

    const float4* row = (const float4*)(data + (size_t)r * TLEN);
    float4 v[EPT / 4];
#pragma unroll
    for (int i = 0; i < EPT / 4; i++) v[i] = __ldg(&row[t * (EPT / 4) + i]);

    if (t == 0) s_y0 = v[0].x;
    __syncthreads();
    float y0 = s_y0;

    float H = 0.0f;
#pragma unroll
    for (int i = 0; i < EPT / 4; i++) {
        H = fmaf(a, H, v[i].x); H = fmaf(a, H, v[i].y);
        H = fmaf(a, H, v[i].z); H = fmaf(a, H, v[i].w);
    }
    float A = a;                           // a^32 via 5 squarings
    A *= A; A *= A; A *= A; A *= A; A *= A;
    float C = sigma * H;

    sA[t] = A; sC[t] = C;
    __syncthreads();
#pragma unroll
    for (int off = 1; off < TPB; off <<= 1) {
        float pa = 1.0f, pc = 0.0f;
        if (t >= off) { pa = sA[t - off]; pc = sC[t - off]; }
        __syncthreads();
        if (t >= off) { sC[t] = fmaf(sA[t], pc, sC[t]); sA[t] *= pa; }
        __syncthreads();
    }
    float L = (t == 0) ? y0 : fmaf(sA[t - 1], y0, sC[t - 1]);

    float4* out = (float4*)(g_filt + (size_t)r * TLEN) + t * (EPT / 4);
#pragma unroll
    for (int i = 0; i < EPT / 4; i++) {
        float4 y = v[i];
        float4 f;
        f.x = L; L = fmaf(sigma, y.x - L, L);
        f.y = L; L = fmaf(sigma, y.y - L, L);
        f.z = L; L = fmaf(sigma, y.z - L, L);
        f.w = L; L = fmaf(sigma, y.w - L, L);
        out[i] = f;
    }
}

// ---------------------------------------------------------------------------
// K3: out[b][t] = data[b][t] - filt[bestRow[b]][t] + broadcast preds.
// Plain (caching) loads and stores — keep everything L2-resident across
// graph replays (working set fits in L2).
// ---------------------------------------------------------------------------
__global__ void __launch_bounds__(256) diff_kernel(const float* __restrict__ data,
                                                   float* __restrict__ out) {
    const int rowq = TLEN / 4;
    int i = blockIdx.x * blockDim.x + threadIdx.x;
    if (i < BATCH * rowq) {
        int b = i / rowq;
        int c = i - b * rowq;
        int r = g_bestRow[b];
        float4 d = __ldg((const float4*)data + i);
        float4 f = __ldg((const float4*)g_filt + (size_t)r * rowq + c);
        float4 o;
        o.x = d.x - f.x; o.y = d.y - f.y; o.z = d.z - f.z; o.w = d.w - f.w;
        ((float4*)out)[i] = o;
    }
    if (i < BATCH * (PRED / 4)) {          // preds: 16 float4 per row
        int b = i >> 4;
        float val = g_levels[b * NSIG + g_sigIdx[b]];
        float4 o = make_float4(val, val, val, val);
        ((float4*)out)[BATCH * rowq + i] = o;
    }
}

// ---------------------------------------------------------------------------
extern "C" void kernel_launch(void* const* d_in, const int* in_sizes, int n_in,
                              void* d_out, int out_size) {
    const float* data = (const float*)d_in[0];
    float* out = (float*)d_out;

    scan_pick_kernel<<<BATCH, 128>>>(data);
    filt_kernel<<<BATCH, 128>>>(data);
    {
        int nq = BATCH * (TLEN / 4);             // float4 count
        diff_kernel<<<(nq + 255) / 256, 256>>>(data, out);
    }
}